// round 2
// baseline (speedup 1.0000x reference)
#include <cuda_runtime.h>
#include <cstdint>
#include <cstddef>

#define NN   65536
#define NE   1048576
#define FIN  128
#define H1D  128
#define H2D  256
#define NC   16

// Scratch (device globals — no allocation allowed)
__device__ float g_y[(size_t)NN * H1D];       // relu(x @ Wp^T + bp)
__device__ float g_pooled[(size_t)NN * H1D];  // segment_max
__device__ float g_h[(size_t)NN * H1D];       // hidden 1
__device__ float g_h2[(size_t)NN * H2D];      // hidden 2

// ---------------------------------------------------------------------------
__global__ void zero_kernel(float4* __restrict__ p, int n4) {
    int i = blockIdx.x * blockDim.x + threadIdx.x;
    int stride = gridDim.x * blockDim.x;
    float4 z = make_float4(0.f, 0.f, 0.f, 0.f);
    for (; i < n4; i += stride) p[i] = z;
}

// ---------------------------------------------------------------------------
// C[M,N] = act( A[M,K] @ B[N,K]^T + bias + (ACC ? C : 0) )
// ACT: 0 = none, 1 = relu, 2 = leaky(0.01)
template <int ACT>
__device__ __forceinline__ float apply_act(float v) {
    if (ACT == 1) return v > 0.f ? v : 0.f;
    if (ACT == 2) return v > 0.f ? v : 0.01f * v;
    return v;
}

template <int ACT, bool ACC>
__global__ __launch_bounds__(256, 2)
void sgemm_kernel(float* __restrict__ C, const float* __restrict__ A,
                  const float* __restrict__ B, const float* __restrict__ bias,
                  int M, int N, int K)
{
    constexpr int BK = 16;
    __shared__ float As[BK][132];   // +4 pad: conflict mitigation + float4 alignment
    __shared__ float Bs[BK][132];

    const int t  = threadIdx.x;
    const int bm = blockIdx.y * 128;
    const int bn = blockIdx.x * 128;
    const int tx = t & 15;          // 0..15 -> N micro-tile
    const int ty = t >> 4;          // 0..15 -> M micro-tile

    float acc[8][8] = {};

    const float* Ab = A + (size_t)bm * K;
    const float* Bb = B + (size_t)bn * K;

    for (int k0 = 0; k0 < K; k0 += BK) {
        #pragma unroll
        for (int i = 0; i < 2; i++) {
            int id  = t + i * 256;       // 0..511
            int row = id >> 2;           // 0..127
            int kk  = (id & 3) << 2;     // 0,4,8,12
            float4 a = *(const float4*)(Ab + (size_t)row * K + k0 + kk);
            As[kk + 0][row] = a.x; As[kk + 1][row] = a.y;
            As[kk + 2][row] = a.z; As[kk + 3][row] = a.w;
            float4 b = *(const float4*)(Bb + (size_t)row * K + k0 + kk);
            Bs[kk + 0][row] = b.x; Bs[kk + 1][row] = b.y;
            Bs[kk + 2][row] = b.z; Bs[kk + 3][row] = b.w;
        }
        __syncthreads();

        #pragma unroll
        for (int k = 0; k < BK; k++) {
            float4 a0 = *(const float4*)&As[k][ty * 8];
            float4 a1 = *(const float4*)&As[k][ty * 8 + 4];
            float4 b0 = *(const float4*)&Bs[k][tx * 8];
            float4 b1 = *(const float4*)&Bs[k][tx * 8 + 4];
            float ra[8] = {a0.x, a0.y, a0.z, a0.w, a1.x, a1.y, a1.z, a1.w};
            float rb[8] = {b0.x, b0.y, b0.z, b0.w, b1.x, b1.y, b1.z, b1.w};
            #pragma unroll
            for (int i = 0; i < 8; i++)
                #pragma unroll
                for (int j = 0; j < 8; j++)
                    acc[i][j] = fmaf(ra[i], rb[j], acc[i][j]);
        }
        __syncthreads();
    }

    float bvals[8];
    #pragma unroll
    for (int j = 0; j < 8; j++)
        bvals[j] = bias ? bias[bn + tx * 8 + j] : 0.0f;

    #pragma unroll
    for (int i = 0; i < 8; i++) {
        size_t ro = (size_t)(bm + ty * 8 + i) * N + bn + tx * 8;
        #pragma unroll
        for (int jj = 0; jj < 8; jj += 4) {
            float4 v;
            v.x = acc[i][jj + 0] + bvals[jj + 0];
            v.y = acc[i][jj + 1] + bvals[jj + 1];
            v.z = acc[i][jj + 2] + bvals[jj + 2];
            v.w = acc[i][jj + 3] + bvals[jj + 3];
            if (ACC) {
                float4 c = *(const float4*)(C + ro + jj);
                v.x += c.x; v.y += c.y; v.z += c.z; v.w += c.w;
            }
            v.x = apply_act<ACT>(v.x); v.y = apply_act<ACT>(v.y);
            v.z = apply_act<ACT>(v.z); v.w = apply_act<ACT>(v.w);
            *(float4*)(C + ro + jj) = v;
        }
    }
}

// ---------------------------------------------------------------------------
// pooled[dst] = max over edges of y[src]   (atomicMax on non-negative floats
// via int bit-pattern ordering; check-before-atomic is race-safe because
// pooled is monotone non-decreasing — stale reads only cost extra atomics)
__global__ void edge_max_kernel(float* __restrict__ pooled, const float* __restrict__ y,
                                const int* __restrict__ src, const int* __restrict__ dst)
{
    int gw   = (blockIdx.x * blockDim.x + threadIdx.x) >> 5;
    int lane = threadIdx.x & 31;
    int nw   = (gridDim.x * blockDim.x) >> 5;
    for (int e = gw; e < NE; e += nw) {
        int s = __ldg(src + e);
        int d = __ldg(dst + e);
        float4 v = *(const float4*)(y + (size_t)s * H1D + lane * 4);
        float* dp = pooled + (size_t)d * H1D + lane * 4;
        float4 cur = __ldcg((const float4*)dp);
        if (v.x > cur.x) atomicMax((int*)dp + 0, __float_as_int(v.x));
        if (v.y > cur.y) atomicMax((int*)dp + 1, __float_as_int(v.y));
        if (v.z > cur.z) atomicMax((int*)dp + 2, __float_as_int(v.z));
        if (v.w > cur.w) atomicMax((int*)dp + 3, __float_as_int(v.w));
    }
}

// ---------------------------------------------------------------------------
// out[n, c] = sigmoid( h2[n, :] . W2[c, :] + b2[c] ),  N=16 classes, K=256
__global__ __launch_bounds__(256)
void head_kernel(float* __restrict__ out, const float* __restrict__ h2,
                 const float* __restrict__ W2, const float* __restrict__ b2)
{
    __shared__ float sW[H2D][NC];        // transposed: sW[k][c]
    __shared__ float sh[16][H2D + 4];

    int t = threadIdx.x;
    #pragma unroll
    for (int i = 0; i < 16; i++) {
        int idx = t + i * 256;           // 0..4095, coalesced over W2
        int c = idx >> 8, k = idx & 255;
        sW[k][c] = W2[idx];
    }
    int r0 = blockIdx.x * 16;
    #pragma unroll
    for (int i = 0; i < 4; i++) {
        int vid = t + i * 256;           // 0..1023 float4 slots
        int row = vid >> 6;              // 0..15
        int kv  = (vid & 63) << 2;
        *(float4*)&sh[row][kv] = *(const float4*)(h2 + (size_t)(r0 + row) * H2D + kv);
    }
    __syncthreads();

    int row = t >> 4, col = t & 15;
    float s = 0.f;
    #pragma unroll 8
    for (int k = 0; k < H2D; k++)
        s = fmaf(sh[row][k], sW[k][col], s);
    s += b2[col];
    out[(size_t)(r0 + row) * NC + col] = 1.0f / (1.0f + expf(-s));
}

// ---------------------------------------------------------------------------
extern "C" void kernel_launch(void* const* d_in, const int* in_sizes, int n_in,
                              void* d_out, int out_size)
{
    const float* x  = (const float*)d_in[0];
    const float* Wp = (const float*)d_in[1];
    const float* bp = (const float*)d_in[2];
    const float* Ws = (const float*)d_in[3];
    const float* Wn = (const float*)d_in[4];
    const float* bn = (const float*)d_in[5];
    const float* W1 = (const float*)d_in[6];
    const float* b1 = (const float*)d_in[7];
    const float* W2 = (const float*)d_in[8];
    const float* b2 = (const float*)d_in[9];
    const int*  src = (const int*)d_in[10];
    const int*  dst = (const int*)d_in[11];
    float* out = (float*)d_out;

    float *y, *pooled, *h, *h2;
    cudaGetSymbolAddress((void**)&y,      g_y);
    cudaGetSymbolAddress((void**)&pooled, g_pooled);
    cudaGetSymbolAddress((void**)&h,      g_h);
    cudaGetSymbolAddress((void**)&h2,     g_h2);

    // pooled = 0 (== segment_max floor after the isneginf->0 rewrite)
    zero_kernel<<<1024, 256>>>((float4*)pooled, NN * H1D / 4);

    // y = relu(x @ Wp^T + bp)   [hoisted per-NODE instead of per-EDGE: 16x fewer FLOPs]
    sgemm_kernel<1, false><<<dim3(1, NN / 128), 256>>>(y, x, Wp, bp, NN, H1D, FIN);

    // pooled = segment_max(y[src], dst)
    edge_max_kernel<<<2048, 256>>>(pooled, y, src, dst);

    // h = leaky( x @ Ws^T + pooled @ Wn^T + bn )   (two passes, second accumulates)
    sgemm_kernel<0, false><<<dim3(1, NN / 128), 256>>>(h, x, Ws, nullptr, NN, H1D, FIN);
    sgemm_kernel<2, true ><<<dim3(1, NN / 128), 256>>>(h, pooled, Wn, bn, NN, H1D, H1D);

    // h2 = leaky( h @ W1^T + b1 )
    sgemm_kernel<2, false><<<dim3(2, NN / 128), 256>>>(h2, h, W1, b1, NN, H2D, H1D);

    // out = sigmoid( h2 @ W2^T + b2 )
    head_kernel<<<NN / 16, 256>>>(out, h2, W2, b2);
}

// round 4
// speedup vs baseline: 1.6576x; 1.6576x over previous
#include <cuda_runtime.h>
#include <cstdint>
#include <cstddef>

#define NN   65536
#define NE   1048576
#define FIN  128
#define H1D  128
#define H2D  256
#define NC   16

// Scratch (device globals — no allocation allowed)
__device__ float g_y[(size_t)NN * H1D];       // relu(x @ Wp^T + bp)
__device__ float g_pooled[(size_t)NN * H1D];  // segment_max
__device__ float g_h[(size_t)NN * H1D];       // hidden 1
__device__ float g_h2[(size_t)NN * H2D];      // hidden 2

// ---------------------------------------------------------------------------
__global__ void zero_kernel(float4* __restrict__ p, int n4) {
    int i = blockIdx.x * blockDim.x + threadIdx.x;
    int stride = gridDim.x * blockDim.x;
    float4 z = make_float4(0.f, 0.f, 0.f, 0.f);
    for (; i < n4; i += stride) p[i] = z;
}

// ---------------------------------------------------------------------------
// ACT: 0 = none, 1 = relu, 2 = leaky(0.01)
template <int ACT>
__device__ __forceinline__ float apply_act(float v) {
    if (ACT == 1) return v > 0.f ? v : 0.f;
    if (ACT == 2) return v > 0.f ? v : 0.01f * v;
    return v;
}

__device__ __forceinline__ uint32_t f2tf32(float f) {
    uint32_t u;
    asm("cvt.rna.tf32.f32 %0, %1;" : "=r"(u) : "f"(f));
    return u;
}

__device__ __forceinline__ void mma8(float* d, const uint32_t* a, const uint32_t* b) {
    asm volatile(
        "mma.sync.aligned.m16n8k8.row.col.f32.tf32.tf32.f32 "
        "{%0,%1,%2,%3}, {%4,%5,%6,%7}, {%8,%9}, {%0,%1,%2,%3};\n"
        : "+f"(d[0]), "+f"(d[1]), "+f"(d[2]), "+f"(d[3])
        : "r"(a[0]), "r"(a[1]), "r"(a[2]), "r"(a[3]), "r"(b[0]), "r"(b[1]));
}

__device__ __forceinline__ void cp16(uint32_t s, const void* g) {
    asm volatile("cp.async.cg.shared.global [%0], [%1], 16;\n" :: "r"(s), "l"(g));
}

// ---------------------------------------------------------------------------
// C[M,N] = act( A1[M,128] @ B1[N,128]^T  (+ A2 @ B2^T if DUAL)  + bias )
// Row-major everywhere. M, N multiples of 128. K fixed at 128 per source.
// tf32 tensor-core GEMM: BM=128, BN=128, BK=32, 2-stage cp.async pipeline,
// 8 warps in a 2x4 (m x n) grid, warp tile 64x32, m16n8k8 fragments.
// Smem stride 36 floats -> fragment LDS is conflict-free: bank = (4g+q)%32.
#define GEMM_SMEM_BYTES (4 * 128 * 36 * 4)   // 2 stages x (A+B) x 128x36 floats

template <int ACT, bool DUAL>
__global__ __launch_bounds__(256, 2)
void mma_gemm(float* __restrict__ C,
              const float* __restrict__ A1, const float* __restrict__ B1,
              const float* __restrict__ A2, const float* __restrict__ B2,
              const float* __restrict__ bias, int N)
{
    constexpr int K = 128, BK = 32, LDSW = 36;
    constexpr int KT = DUAL ? 8 : 4;
    constexpr int BUF = 128 * LDSW;          // floats per tile buffer

    extern __shared__ float smem[];
    float* As[2] = { smem,           smem + BUF     };
    float* Bs[2] = { smem + 2*BUF,   smem + 3*BUF   };

    const int t    = threadIdx.x;
    const int lane = t & 31, w = t >> 5;
    const int wm = w >> 2, wn = w & 3;       // 2 x 4 warp grid
    const int g  = lane >> 2, q = lane & 3;  // groupID, threadID-in-group
    const int bm = blockIdx.y * 128, bn = blockIdx.x * 128;

    float acc[4][4][4];
    #pragma unroll
    for (int i = 0; i < 4; i++)
        #pragma unroll
        for (int j = 0; j < 4; j++)
            #pragma unroll
            for (int v = 0; v < 4; v++) acc[i][j][v] = 0.f;

    auto load_stage = [&](int kt, int st) {
        const float* Ap = (DUAL && kt >= 4) ? A2 : A1;
        const float* Bp = (DUAL && kt >= 4) ? B2 : B1;
        const int k0 = (kt & 3) * BK;
        #pragma unroll
        for (int i = 0; i < 4; i++) {
            int id  = t + i * 256;
            int row = id >> 3;
            int kv  = (id & 7) << 2;
            cp16((uint32_t)__cvta_generic_to_shared(&As[st][row * LDSW + kv]),
                 Ap + (size_t)(bm + row) * K + k0 + kv);
            cp16((uint32_t)__cvta_generic_to_shared(&Bs[st][row * LDSW + kv]),
                 Bp + (size_t)(bn + row) * K + k0 + kv);
        }
        asm volatile("cp.async.commit_group;\n");
    };

    load_stage(0, 0);

    #pragma unroll
    for (int kt = 0; kt < KT; kt++) {
        const int st = kt & 1;
        if (kt + 1 < KT) {
            load_stage(kt + 1, st ^ 1);
            asm volatile("cp.async.wait_group 1;\n");
        } else {
            asm volatile("cp.async.wait_group 0;\n");
        }
        __syncthreads();

        const float* Aw = &As[st][(wm * 64) * LDSW];
        const float* Bw = &Bs[st][(wn * 32) * LDSW];

        #pragma unroll
        for (int kk = 0; kk < 4; kk++) {
            const int kb = kk * 8;
            uint32_t bf[4][2];
            #pragma unroll
            for (int nj = 0; nj < 4; nj++) {
                bf[nj][0] = f2tf32(Bw[(nj * 8 + g) * LDSW + kb + q]);
                bf[nj][1] = f2tf32(Bw[(nj * 8 + g) * LDSW + kb + q + 4]);
            }
            #pragma unroll
            for (int mi = 0; mi < 4; mi++) {
                uint32_t af[4];
                af[0] = f2tf32(Aw[(mi * 16 + g    ) * LDSW + kb + q    ]);
                af[1] = f2tf32(Aw[(mi * 16 + g + 8) * LDSW + kb + q    ]);
                af[2] = f2tf32(Aw[(mi * 16 + g    ) * LDSW + kb + q + 4]);
                af[3] = f2tf32(Aw[(mi * 16 + g + 8) * LDSW + kb + q + 4]);
                #pragma unroll
                for (int nj = 0; nj < 4; nj++)
                    mma8(acc[mi][nj], af, bf[nj]);
            }
        }
        __syncthreads();
    }

    // Epilogue: c0,c1 at (g, 2q..2q+1), c2,c3 at (g+8, ...)
    #pragma unroll
    for (int mi = 0; mi < 4; mi++) {
        const int r0 = bm + wm * 64 + mi * 16 + g;
        #pragma unroll
        for (int nj = 0; nj < 4; nj++) {
            const int c = bn + wn * 32 + nj * 8 + q * 2;
            const float bx = bias[c], by = bias[c + 1];
            float2 v0, v1;
            v0.x = apply_act<ACT>(acc[mi][nj][0] + bx);
            v0.y = apply_act<ACT>(acc[mi][nj][1] + by);
            v1.x = apply_act<ACT>(acc[mi][nj][2] + bx);
            v1.y = apply_act<ACT>(acc[mi][nj][3] + by);
            *(float2*)&C[(size_t)r0 * N + c]       = v0;
            *(float2*)&C[(size_t)(r0 + 8) * N + c] = v1;
        }
    }
}

// ---------------------------------------------------------------------------
// pooled[dst] = max over edges of y[src]   (atomicMax on non-negative floats
// via int bit-pattern ordering; check-before-atomic is race-safe because
// pooled is monotone non-decreasing — stale reads only cost extra atomics)
__global__ void edge_max_kernel(float* __restrict__ pooled, const float* __restrict__ y,
                                const int* __restrict__ src, const int* __restrict__ dst)
{
    int gw   = (blockIdx.x * blockDim.x + threadIdx.x) >> 5;
    int lane = threadIdx.x & 31;
    int nw   = (gridDim.x * blockDim.x) >> 5;
    for (int e = gw; e < NE; e += nw) {
        int s = __ldg(src + e);
        int d = __ldg(dst + e);
        float4 v = *(const float4*)(y + (size_t)s * H1D + lane * 4);
        float* dp = pooled + (size_t)d * H1D + lane * 4;
        float4 cur = __ldcg((const float4*)dp);
        if (v.x > cur.x) atomicMax((int*)dp + 0, __float_as_int(v.x));
        if (v.y > cur.y) atomicMax((int*)dp + 1, __float_as_int(v.y));
        if (v.z > cur.z) atomicMax((int*)dp + 2, __float_as_int(v.z));
        if (v.w > cur.w) atomicMax((int*)dp + 3, __float_as_int(v.w));
    }
}

// ---------------------------------------------------------------------------
// out[n, c] = sigmoid( h2[n, :] . W2[c, :] + b2[c] ),  N=16 classes, K=256
__global__ __launch_bounds__(256)
void head_kernel(float* __restrict__ out, const float* __restrict__ h2,
                 const float* __restrict__ W2, const float* __restrict__ b2)
{
    __shared__ float sW[H2D][NC];        // transposed: sW[k][c]
    __shared__ float sh[16][H2D + 4];

    int t = threadIdx.x;
    #pragma unroll
    for (int i = 0; i < 16; i++) {
        int idx = t + i * 256;           // 0..4095, coalesced over W2
        int c = idx >> 8, k = idx & 255;
        sW[k][c] = W2[idx];
    }
    int r0 = blockIdx.x * 16;
    #pragma unroll
    for (int i = 0; i < 4; i++) {
        int vid = t + i * 256;           // 0..1023 float4 slots
        int row = vid >> 6;              // 0..15
        int kv  = (vid & 63) << 2;
        *(float4*)&sh[row][kv] = *(const float4*)(h2 + (size_t)(r0 + row) * H2D + kv);
    }
    __syncthreads();

    int row = t >> 4, col = t & 15;
    float s = 0.f;
    #pragma unroll 8
    for (int k = 0; k < H2D; k++)
        s = fmaf(sh[row][k], sW[k][col], s);
    s += b2[col];
    out[(size_t)(r0 + row) * NC + col] = 1.0f / (1.0f + expf(-s));
}

// ---------------------------------------------------------------------------
extern "C" void kernel_launch(void* const* d_in, const int* in_sizes, int n_in,
                              void* d_out, int out_size)
{
    const float* x  = (const float*)d_in[0];
    const float* Wp = (const float*)d_in[1];
    const float* bp = (const float*)d_in[2];
    const float* Ws = (const float*)d_in[3];
    const float* Wn = (const float*)d_in[4];
    const float* bn = (const float*)d_in[5];
    const float* W1 = (const float*)d_in[6];
    const float* b1 = (const float*)d_in[7];
    const float* W2 = (const float*)d_in[8];
    const float* b2 = (const float*)d_in[9];
    const int*  src = (const int*)d_in[10];
    const int*  dst = (const int*)d_in[11];
    float* out = (float*)d_out;

    float *y, *pooled, *h, *h2;
    cudaGetSymbolAddress((void**)&y,      g_y);
    cudaGetSymbolAddress((void**)&pooled, g_pooled);
    cudaGetSymbolAddress((void**)&h,      g_h);
    cudaGetSymbolAddress((void**)&h2,     g_h2);

    static bool attr_set = false;
    if (!attr_set) {
        cudaFuncSetAttribute(mma_gemm<1, false>, cudaFuncAttributeMaxDynamicSharedMemorySize, GEMM_SMEM_BYTES);
        cudaFuncSetAttribute(mma_gemm<2, true >, cudaFuncAttributeMaxDynamicSharedMemorySize, GEMM_SMEM_BYTES);
        cudaFuncSetAttribute(mma_gemm<2, false>, cudaFuncAttributeMaxDynamicSharedMemorySize, GEMM_SMEM_BYTES);
        attr_set = true;
    }

    // pooled = 0 (== segment_max floor after the isneginf->0 rewrite)
    zero_kernel<<<1024, 256>>>((float4*)pooled, NN * H1D / 4);

    // y = relu(x @ Wp^T + bp)   [hoisted per-NODE instead of per-EDGE]
    mma_gemm<1, false><<<dim3(1, NN / 128), 256, GEMM_SMEM_BYTES>>>(
        y, x, Wp, nullptr, nullptr, bp, H1D);

    // pooled = segment_max(y[src], dst)
    edge_max_kernel<<<2048, 256>>>(pooled, y, src, dst);

    // h = leaky( x @ Ws^T + pooled @ Wn^T + bn )   — fused dual-source GEMM
    mma_gemm<2, true><<<dim3(1, NN / 128), 256, GEMM_SMEM_BYTES>>>(
        h, x, Ws, pooled, Wn, bn, H1D);

    // h2 = leaky( h @ W1^T + b1 )
    mma_gemm<2, false><<<dim3(2, NN / 128), 256, GEMM_SMEM_BYTES>>>(
        h2, h, W1, nullptr, nullptr, b1, H2D);

    // out = sigmoid( h2 @ W2^T + b2 )
    head_kernel<<<NN / 16, 256>>>(out, h2, W2, b2);
}